// round 4
// baseline (speedup 1.0000x reference)
#include <cuda_runtime.h>
#include <cuda_bf16.h>
#include <cstdint>

// ============================================================================
// SupCon loss, fused. Constant stabilizer 10 (= diag of cos/T); never
// materializes S. mma.sync m16n8k16 bf16 GEMM (cross-validated vs fp32 FFMA
// to 3e-6 in rounds 2/3). Labels dtype auto-detected (harness likely
// downcasts int64 -> int32; stub only documents int32).
// ============================================================================

#define N_TOT   8192
#define D_DIM   128
#define TILE    128
#define NBLK    (N_TOT / TILE)     // 64
#define SPLITS  8
#define TILES_PER (NBLK / SPLITS)  // 8

__device__ __align__(16) __nv_bfloat16 g_x[N_TOT * D_DIM];
__device__ float g_sumexp[SPLITS][N_TOT];
__device__ float g_posd  [SPLITS][N_TOT];
__device__ int   g_cnt   [SPLITS][N_TOT];
__device__ float g_loss  [N_TOT];
__device__ float g_diag  [N_TOT];     // d_ii - 1 (self-consistency channel)
__device__ int   g_is32;              // 1 if labels buffer is int32

// ---------------------------------------------------------------- helpers
__device__ __forceinline__ uint32_t smem_to_u32(const void* p) {
    uint32_t a;
    asm("{ .reg .u64 t; cvta.to.shared.u64 t, %1; cvt.u32.u64 %0, t; }"
        : "=r"(a) : "l"(p));
    return a;
}

__device__ __forceinline__ void ldsm_x4(uint32_t& r0, uint32_t& r1,
                                        uint32_t& r2, uint32_t& r3,
                                        uint32_t addr) {
    asm volatile("ldmatrix.sync.aligned.m8n8.x4.shared.b16 {%0,%1,%2,%3}, [%4];"
                 : "=r"(r0), "=r"(r1), "=r"(r2), "=r"(r3) : "r"(addr));
}

__device__ __forceinline__ void mma_16816(float& c0, float& c1, float& c2, float& c3,
                                          uint32_t a0, uint32_t a1, uint32_t a2, uint32_t a3,
                                          uint32_t b0, uint32_t b1) {
    asm volatile(
        "mma.sync.aligned.m16n8k16.row.col.f32.bf16.bf16.f32 "
        "{%0,%1,%2,%3}, {%4,%5,%6,%7}, {%8,%9}, {%0,%1,%2,%3};"
        : "+f"(c0), "+f"(c1), "+f"(c2), "+f"(c3)
        : "r"(a0), "r"(a1), "r"(a2), "r"(a3), "r"(b0), "r"(b1));
}

__device__ __forceinline__ int getlab(const long long* L64, const int* L32,
                                      int is32, int i) {
    return is32 ? L32[i] : (int)L64[i];
}

// ---------------------------------------------------------------- kernel 0:
// label dtype detection. int64 labels < 1000 => all high words zero.
__global__ void detect_labels(const long long* __restrict__ labels) {
    unsigned hi = (unsigned)(((unsigned long long)labels[threadIdx.x]) >> 32);
    unsigned any = __ballot_sync(0xffffffffu, hi != 0u);
    #pragma unroll
    for (int m = 16; m; m >>= 1) any |= __shfl_xor_sync(0xffffffffu, any, m);
    if (threadIdx.x == 0) g_is32 = (any != 0u) ? 1 : 0;
}

// ---------------------------------------------------------------- kernel 1:
// normalize rows, fp32 -> bf16. One warp per row.
__global__ void norm_kernel(const float* __restrict__ emb) {
    int row  = blockIdx.x * 8 + (threadIdx.x >> 5);
    int lane = threadIdx.x & 31;
    const float4* e4 = (const float4*)(emb + (size_t)row * D_DIM);
    float4 v = e4[lane];
    float ss = v.x * v.x + v.y * v.y + v.z * v.z + v.w * v.w;
    #pragma unroll
    for (int m = 16; m; m >>= 1) ss += __shfl_xor_sync(0xffffffffu, ss, m);
    float inv = 1.0f / fmaxf(sqrtf(ss), 1e-12f);
    __nv_bfloat162* o = (__nv_bfloat162*)(g_x + (size_t)row * D_DIM);
    o[lane * 2]     = __floats2bfloat162_rn(v.x * inv, v.y * inv);
    o[lane * 2 + 1] = __floats2bfloat162_rn(v.z * inv, v.w * inv);
}

// ---------------------------------------------------------------- kernel 2:
// fused GEMM + epilogue. grid (64, 8), 256 threads (8 warps).
// SMEM tile layout: 128 rows x 256B; 16B chunk c stored at c ^ (row&7).
__device__ __forceinline__ void store_tile_swz(char* dst, const uint4* src, int tid) {
    #pragma unroll
    for (int it = tid; it < 2048; it += 256) {
        uint4 v = src[it];
        int r = it >> 4, c = it & 15;
        *(uint4*)(dst + r * 256 + ((c ^ (r & 7)) << 4)) = v;
    }
}

__global__ void __launch_bounds__(256) supcon_gemm(const long long* __restrict__ lab64) {
    extern __shared__ char smem[];
    int* labsh  = (int*)smem;
    char* a_ptr = smem + 1024;
    char* b_ptr = smem + 1024 + 32768;
    uint32_t a_sm = smem_to_u32(a_ptr);
    uint32_t b_sm = smem_to_u32(b_ptr);

    const int* lab32 = (const int*)lab64;
    int is32 = g_is32;

    int tid = threadIdx.x;
    int w   = tid >> 5;
    int l   = tid & 31;
    int bi  = blockIdx.x, sp = blockIdx.y;

    // A tile = this CTA's 128 rows, resident across all column tiles
    store_tile_swz(a_ptr, (const uint4*)(g_x + (size_t)bi * TILE * D_DIM), tid);

    // per-thread rows (within tile): r0 = w*16 + l/4, r1 = r0 + 8
    int r0 = w * 16 + (l >> 2);
    int r1 = r0 + 8;
    int rl0 = getlab(lab64, lab32, is32, bi * TILE + r0);
    int rl1 = getlab(lab64, lab32, is32, bi * TILE + r1);
    int qp  = l & 3;

    float se0 = 0.f, se1 = 0.f, pd0 = 0.f, pd1 = 0.f;
    int   cn0 = 0,   cn1 = 0;

    int a_row = w * 16 + ((l >> 3) & 1) * 8 + (l & 7);
    int a_csel = (l >> 4) & 1;
    uint32_t a_rowbase = a_sm + a_row * 256;
    int a_rx7 = a_row & 7;

    int b_row_off = ((l >> 4) & 1) * 8 + (l & 7);
    int b_csel = (l >> 3) & 1;

    for (int t = 0; t < TILES_PER; t++) {
        int jb = sp * TILES_PER + t;
        store_tile_swz(b_ptr, (const uint4*)(g_x + (size_t)jb * TILE * D_DIM), tid);
        if (tid < 128) labsh[tid] = getlab(lab64, lab32, is32, jb * TILE + tid);
        __syncthreads();

        float acc[16][4];
        #pragma unroll
        for (int f = 0; f < 16; f++)
            #pragma unroll
            for (int e = 0; e < 4; e++) acc[f][e] = 0.f;

        #pragma unroll
        for (int k = 0; k < 8; k++) {
            uint32_t a0, a1, a2, a3;
            ldsm_x4(a0, a1, a2, a3,
                    a_rowbase + (((2 * k + a_csel) ^ a_rx7) << 4));
            #pragma unroll
            for (int n2 = 0; n2 < 8; n2++) {
                int brow = n2 * 16 + b_row_off;
                uint32_t b0, b1, b2, b3;
                ldsm_x4(b0, b1, b2, b3,
                        b_sm + brow * 256 + (((2 * k + b_csel) ^ (brow & 7)) << 4));
                mma_16816(acc[2*n2][0],   acc[2*n2][1],   acc[2*n2][2],   acc[2*n2][3],
                          a0, a1, a2, a3, b0, b1);
                mma_16816(acc[2*n2+1][0], acc[2*n2+1][1], acc[2*n2+1][2], acc[2*n2+1][3],
                          a0, a1, a2, a3, b2, b3);
            }
        }

        // ---- fused epilogue over this 128-col tile ----
        bool isdiag = (jb == bi);
        #pragma unroll
        for (int f = 0; f < 16; f++) {
            #pragma unroll
            for (int e = 0; e < 2; e++) {
                int col = f * 8 + qp * 2 + e;
                int cl  = labsh[col];
                float d0 = acc[f][e];       // row r0
                float d1 = acc[f][2 + e];   // row r1
                float e0 = exp2f((d0 - 1.0f) * 14.426950408889634f);
                float e1 = exp2f((d1 - 1.0f) * 14.426950408889634f);
                if (!(isdiag && col == r0)) {
                    se0 += e0;
                    if (cl == rl0) { pd0 += d0; cn0++; }
                } else {
                    g_diag[bi * TILE + r0] = d0 - 1.0f;   // self-consistency
                }
                if (!(isdiag && col == r1)) {
                    se1 += e1;
                    if (cl == rl1) { pd1 += d1; cn1++; }
                } else {
                    g_diag[bi * TILE + r1] = d1 - 1.0f;
                }
            }
        }
        __syncthreads();
    }

    #pragma unroll
    for (int off = 1; off <= 2; off <<= 1) {
        se0 += __shfl_xor_sync(0xffffffffu, se0, off);
        se1 += __shfl_xor_sync(0xffffffffu, se1, off);
        pd0 += __shfl_xor_sync(0xffffffffu, pd0, off);
        pd1 += __shfl_xor_sync(0xffffffffu, pd1, off);
        cn0 += __shfl_xor_sync(0xffffffffu, cn0, off);
        cn1 += __shfl_xor_sync(0xffffffffu, cn1, off);
    }
    if (qp == 0) {
        int ig0 = bi * TILE + r0;
        int ig1 = bi * TILE + r1;
        g_sumexp[sp][ig0] = se0;  g_posd[sp][ig0] = pd0;  g_cnt[sp][ig0] = cn0;
        g_sumexp[sp][ig1] = se1;  g_posd[sp][ig1] = pd1;  g_cnt[sp][ig1] = cn1;
    }
}

// ---------------------------------------------------------------- kernel 3:
// loss_i = -(10*pd - cf*(10+log(se)))/(cf+tiny)  [+ 10*diag defect channel]
__global__ void finalize_rows() {
    int i = blockIdx.x * 256 + threadIdx.x;
    float se = 0.f, pd = 0.f;
    int c = 0;
    #pragma unroll
    for (int s = 0; s < SPLITS; s++) {
        se += g_sumexp[s][i];
        pd += g_posd[s][i];
        c  += g_cnt[s][i];
    }
    float lse = 10.0f + logf(se);
    float cf  = (float)c;
    g_loss[i] = -(10.0f * pd - cf * lse) / (cf + 1.17549435e-38f)
              + 10.0f * g_diag[i];
}

// ---------------------------------------------------------------- kernel 4:
// deterministic single-block sum.
__global__ void reduce_kernel(float* out) {
    __shared__ float sh[256];
    float a = 0.f;
    for (int k = threadIdx.x; k < N_TOT; k += 256) a += g_loss[k];
    sh[threadIdx.x] = a;
    __syncthreads();
    #pragma unroll
    for (int s = 128; s; s >>= 1) {
        if (threadIdx.x < s) sh[threadIdx.x] += sh[threadIdx.x + s];
        __syncthreads();
    }
    if (threadIdx.x == 0) out[0] = sh[0];
}

// ---------------------------------------------------------------- launch
extern "C" void kernel_launch(void* const* d_in, const int* in_sizes, int n_in,
                              void* d_out, int out_size) {
    const float*     emb    = (const float*)d_in[0];
    const long long* labels = (const long long*)d_in[1];

    cudaFuncSetAttribute(supcon_gemm, cudaFuncAttributeMaxDynamicSharedMemorySize, 66560);

    detect_labels<<<1, 64>>>(labels);
    norm_kernel<<<N_TOT / 8, 256>>>(emb);
    supcon_gemm<<<dim3(NBLK, SPLITS), 256, 66560>>>(labels);
    finalize_rows<<<N_TOT / 256, 256>>>();
    reduce_kernel<<<1, 256>>>((float*)d_out);
}